// round 14
// baseline (speedup 1.0000x reference)
#include <cuda_runtime.h>
#include <cstdint>

#define CTOT  512
#define BG    256      // N*G = 32*8 groups
#define CGH   32       // channels per half-group
#define PLANE 4096     // 64*64

__device__ __forceinline__ float sigmoid_exact(float z) {
    return __fdividef(1.0f, 1.0f + __expf(-z));
}
// 1-MUFU sigmoid: sigmoid(z) = 0.5*tanh(z/2) + 0.5
__device__ __forceinline__ float sigmoid_fast(float z) {
    float t;
    asm("tanh.approx.f32 %0, %1;" : "=f"(t) : "f"(z * 0.5f));
    return fmaf(0.5f, t, 0.5f);
}

// ---------------------------------------------------------------------------
// KS: whole spatial branch for one bg group per block.
//   1024 threads; warp w owns x1 plane w (32 planes).
//   __launch_bounds__(1024, 2): two ks blocks per SM so phase-2/barrier
//   bubbles of one block are filled by the other's memory phases.
// ---------------------------------------------------------------------------
__global__ __launch_bounds__(1024, 2) void ks_kernel(
    const float* __restrict__ x,
    const float* __restrict__ w1,  const float* __restrict__ b1,
    const float* __restrict__ gng, const float* __restrict__ gnb,
    const float* __restrict__ wh,  const float* __restrict__ bh,
    const float* __restrict__ wwv, const float* __restrict__ bw,
    float* __restrict__ out)
{
    const int bg   = blockIdx.x;     // 0..255
    const int n    = bg >> 3;
    const int g    = bg & 7;
    const int t    = threadIdx.x;    // 0..1023
    const int wid  = t >> 5;         // plane index 0..31
    const int lane = t & 31;

    // smem: s_row/s_col double as s_ah/s_aw after conv1 consumes them
    __shared__ float s_row[32][64];      // x_h (row means)  -> later a_h
    __shared__ float s_col[32][64];      // x_w (col means)  -> later a_w
    __shared__ float s_xs[32];           // plane means
    __shared__ float ybuf[32][128];      // conv1 out / normalized
    __shared__ float w1s[1024], whs[1024], wws[1024];
    __shared__ float b1s[32], bhs[32], bws[32], gngs[32], gnbs[32];
    __shared__ float mus[32], rstds[32];

    // weights (independent of everything; issued first)
    w1s[t] = w1[t];
    whs[t] = wh[t];
    wws[t] = wwv[t];
    if (t < 32) {
        b1s[t] = b1[t]; bhs[t] = bh[t]; bws[t] = bw[t];
        gngs[t] = gng[t]; gnbs[t] = gnb[t];
    }

    // ---------------- phase 1: reductions (warp w = plane w) ----------------
    const float4* p4 = (const float4*)(x + (size_t)(n * CTOT + g * 64 + 32 + wid) * PLANE);
    // lane reads float4 j = lane + 32*i : row = (lane>>4) + 2*i, cols 4*(lane&15)..+3
    float4 colacc = make_float4(0.f, 0.f, 0.f, 0.f);
    #pragma unroll 8
    for (int i = 0; i < 32; i++) {
        float4 v = p4[lane + 32 * i];            // default policy: retain in L2
        colacc.x += v.x; colacc.y += v.y; colacc.z += v.z; colacc.w += v.w;
        float s = v.x + v.y + v.z + v.w;
        s += __shfl_xor_sync(0xffffffffu, s, 8);
        s += __shfl_xor_sync(0xffffffffu, s, 4);
        s += __shfl_xor_sync(0xffffffffu, s, 2);
        s += __shfl_xor_sync(0xffffffffu, s, 1);
        if ((lane & 15) == 0)
            s_row[wid][2 * i + (lane >> 4)] = s * (1.0f / 64.0f);
    }
    // fold the two half-warps' row sets for columns
    colacc.x += __shfl_xor_sync(0xffffffffu, colacc.x, 16);
    colacc.y += __shfl_xor_sync(0xffffffffu, colacc.y, 16);
    colacc.z += __shfl_xor_sync(0xffffffffu, colacc.z, 16);
    colacc.w += __shfl_xor_sync(0xffffffffu, colacc.w, 16);
    if (lane < 16) {
        float4 cw;
        cw.x = colacc.x * (1.0f / 64.0f);
        cw.y = colacc.y * (1.0f / 64.0f);
        cw.z = colacc.z * (1.0f / 64.0f);
        cw.w = colacc.w * (1.0f / 64.0f);
        ((float4*)s_col[wid])[lane] = cw;
    }
    float cs = colacc.x + colacc.y + colacc.z + colacc.w;
    cs += __shfl_xor_sync(0xffffffffu, cs, 8);
    cs += __shfl_xor_sync(0xffffffffu, cs, 4);
    cs += __shfl_xor_sync(0xffffffffu, cs, 2);
    cs += __shfl_xor_sync(0xffffffffu, cs, 1);
    if (lane == 0) s_xs[wid] = cs * (1.0f / 4096.0f);
    __syncthreads();

    // ---------------- phase 2: conv1 -> GN -> h-swish -> convh/convw --------
    const int p  = t & 127;          // position 0..127
    const int oh = (t >> 7) * 16;    // only meaningful for t<256

    float a1[16];
    if (t < 256) {
        #pragma unroll
        for (int o = 0; o < 16; o++) a1[o] = b1s[oh + o];
        #pragma unroll
        for (int i = 0; i < 32; i++) {
            const float ci = (p < 64) ? s_row[i][p] : s_col[i][p - 64];
            #pragma unroll
            for (int o = 0; o < 16; o++)
                a1[o] += w1s[(oh + o) * 32 + i] * ci;
        }
    }
    __syncthreads();                 // s_row/s_col reads done -> reusable
    if (t < 256) {
        #pragma unroll
        for (int o = 0; o < 16; o++) ybuf[oh + o][p] = a1[o];
    }
    __syncthreads();

    if (t < 256) {                   // GN stats: warp w2 handles 4 channels
        const int w2 = t >> 5, l = t & 31;
        #pragma unroll
        for (int j = 0; j < 4; j++) {
            const int o = w2 * 4 + j;
            float e0 = ybuf[o][l],      e1 = ybuf[o][l + 32],
                  e2 = ybuf[o][l + 64], e3 = ybuf[o][l + 96];
            float s  = e0 + e1 + e2 + e3;
            float ss = e0 * e0 + e1 * e1 + e2 * e2 + e3 * e3;
            #pragma unroll
            for (int off = 16; off > 0; off >>= 1) {
                s  += __shfl_xor_sync(0xffffffffu, s, off);
                ss += __shfl_xor_sync(0xffffffffu, ss, off);
            }
            if (l == 0) {
                float mu  = s * (1.0f / 128.0f);
                float var = ss * (1.0f / 128.0f) - mu * mu;
                mus[o]   = mu;
                rstds[o] = rsqrtf(var + 1e-5f);
            }
        }
    }
    __syncthreads();

    if (t < 256) {                   // normalize + affine + h-swish
        #pragma unroll
        for (int j = 0; j < 16; j++) {
            const int k = oh + j;
            float v = (ybuf[k][p] - mus[k]) * rstds[k] * gngs[k] + gnbs[k];
            float hs = fminf(fmaxf(v + 3.0f, 0.0f), 6.0f) * (1.0f / 6.0f);
            ybuf[k][p] = v * hs;
        }
    }
    __syncthreads();

    if (t < 256) {                   // convh (p<64) -> s_row, convw -> s_col
        const int half = p >> 6;
        const int r    = p & 63;
        const float* wsel = half ? wws : whs;
        const float* bsel = half ? bws : bhs;
        float a2[16];
        #pragma unroll
        for (int o = 0; o < 16; o++) a2[o] = bsel[oh + o];
        #pragma unroll
        for (int i = 0; i < 32; i++) {
            const float ci = ybuf[i][p];
            #pragma unroll
            for (int o = 0; o < 16; o++)
                a2[o] += wsel[(oh + o) * 32 + i] * ci;
        }
        if (half) {
            #pragma unroll
            for (int o = 0; o < 16; o++) s_col[oh + o][r] = a2[o];   // a_w
        } else {
            #pragma unroll
            for (int o = 0; o < 16; o++) s_row[oh + o][r] = a2[o];   // a_h
        }
    }
    __syncthreads();

    // ---------------- phase 3: gate + write (warp w = plane w) --------------
    const float xs = s_xs[wid];
    float4 aw4 = ((float4*)s_col[wid])[lane & 15];
    aw4.x *= xs; aw4.y *= xs; aw4.z *= xs; aw4.w *= xs;

    const int c_prev  = g * 64 + 32 + wid;
    const int c_final = 2 * (c_prev & 255) + (c_prev >> 8);
    float4* o4 = (float4*)(out + (size_t)(n * CTOT + c_final) * PLANE);

    #pragma unroll 8
    for (int i = 0; i < 32; i++) {
        float4 v = __ldcs(&p4[lane + 32 * i]);            // hot in L2
        const float ah = s_row[wid][2 * i + (lane >> 4)];
        v.x *= sigmoid_fast(ah * aw4.x);
        v.y *= sigmoid_fast(ah * aw4.y);
        v.z *= sigmoid_fast(ah * aw4.z);
        v.w *= sigmoid_fast(ah * aw4.w);
        __stcs(&o4[lane + 32 * i], v);
    }
}

// ---------------------------------------------------------------------------
// K1b: x0 channel-gating stream. Independent; runs after ks.
// ---------------------------------------------------------------------------
__global__ __launch_bounds__(256) void k1b_kernel(
    const float* __restrict__ x,
    const float* __restrict__ cweight,
    const float* __restrict__ cbias,
    float* __restrict__ out)
{
    const int cc = blockIdx.x;          // 0..31
    const int bg = blockIdx.y;          // 0..255
    const int n  = bg >> 3;
    const int g  = bg & 7;
    const int t  = threadIdx.x;

    const float4* p4 = (const float4*)(x + (size_t)(n * CTOT + g * 64 + cc) * PLANE);
    float4 v[4];
    #pragma unroll
    for (int i = 0; i < 4; i++) v[i] = __ldcs(&p4[t + 256 * i]);

    float s = 0.f;
    #pragma unroll
    for (int i = 0; i < 4; i++) s += v[i].x + v[i].y + v[i].z + v[i].w;
    __shared__ float ws[8];
    __shared__ float sgate;
    #pragma unroll
    for (int o = 16; o > 0; o >>= 1) s += __shfl_xor_sync(0xffffffffu, s, o);
    if ((t & 31) == 0) ws[t >> 5] = s;
    __syncthreads();
    if (t == 0) {
        float tot = 0.f;
        #pragma unroll
        for (int i = 0; i < 8; i++) tot += ws[i];
        float gap = tot * (1.0f / 4096.0f);
        sgate = sigmoid_exact(cweight[cc] * gap + cbias[cc]);
    }
    __syncthreads();
    const float gate = sgate;

    const int c_prev  = g * 64 + cc;
    const int c_final = 2 * (c_prev & 255) + (c_prev >> 8);
    float4* o4 = (float4*)(out + (size_t)(n * CTOT + c_final) * PLANE);
    #pragma unroll
    for (int i = 0; i < 4; i++) {
        float4 r = v[i];
        r.x *= gate; r.y *= gate; r.z *= gate; r.w *= gate;
        __stcs(&o4[t + 256 * i], r);
    }
}

// ---------------------------------------------------------------------------
extern "C" void kernel_launch(void* const* d_in, const int* in_sizes, int n_in,
                              void* d_out, int out_size)
{
    const float* x       = (const float*)d_in[0];
    const float* cweight = (const float*)d_in[1];
    const float* cbias   = (const float*)d_in[2];
    const float* conv1_w = (const float*)d_in[3];
    const float* conv1_b = (const float*)d_in[4];
    const float* gn_g    = (const float*)d_in[5];
    const float* gn_b    = (const float*)d_in[6];
    const float* convh_w = (const float*)d_in[7];
    const float* convh_b = (const float*)d_in[8];
    const float* convw_w = (const float*)d_in[9];
    const float* convw_b = (const float*)d_in[10];
    float* out = (float*)d_out;

    // spatial branch: 256 bg-monolithic blocks, 2 per SM (one full wave)
    ks_kernel<<<BG, 1024>>>(x, conv1_w, conv1_b, gn_g, gn_b,
                            convh_w, convh_b, convw_w, convw_b, out);

    // channel branch: independent stream
    k1b_kernel<<<dim3(CGH, BG), 256>>>(x, cweight, cbias, out);
}

// round 15
// speedup vs baseline: 1.2550x; 1.2550x over previous
#include <cuda_runtime.h>
#include <cstdint>

#define CTOT  512
#define BG    256      // N*G = 32*8 groups
#define CGH   32       // channels per half-group
#define PLANE 4096     // 64*64

#define NKS   256      // ks-role blocks (one per bg), low bids -> dispatched first
#define NCH   512      // channel-role blocks (16 x0 planes each)

__device__ __forceinline__ float sigmoid_exact(float z) {
    return __fdividef(1.0f, 1.0f + __expf(-z));
}
// 1-MUFU sigmoid: sigmoid(z) = 0.5*tanh(z/2) + 0.5
__device__ __forceinline__ float sigmoid_fast(float z) {
    float t;
    asm("tanh.approx.f32 %0, %1;" : "=f"(t) : "f"(z * 0.5f));
    return fmaf(0.5f, t, 0.5f);
}

// ---------------------------------------------------------------------------
// One kernel, two block roles, occ 1 (one 1024-thr block per SM):
//   bid <  NKS : whole spatial branch for one bg group (32 warps, 32 planes)
//   bid >= NKS : channel branch, 16 x0 planes (4 x 256-thr sub-groups x 4 iters)
// ks blocks take low bids -> wave 1 is pure ks (L2 live window 148*512KB);
// channel blocks fill wave-2's idle SMs and the tail, streaming .cs only.
// ---------------------------------------------------------------------------
__global__ __launch_bounds__(1024, 1) void fused_kernel(
    const float* __restrict__ x,
    const float* __restrict__ cweight, const float* __restrict__ cbias,
    const float* __restrict__ w1,  const float* __restrict__ b1,
    const float* __restrict__ gng, const float* __restrict__ gnb,
    const float* __restrict__ wh,  const float* __restrict__ bh,
    const float* __restrict__ wwv, const float* __restrict__ bw,
    float* __restrict__ out)
{
    // smem (ks role uses everything; channel role reuses s_row/s_col corners)
    __shared__ float s_row[32][64];      // x_h (row means)  -> later a_h
    __shared__ float s_col[32][64];      // x_w (col means)  -> later a_w
    __shared__ float s_xs[32];           // plane means
    __shared__ float ybuf[32][128];      // conv1 out / normalized
    __shared__ float w1s[1024], whs[1024], wws[1024];
    __shared__ float b1s[32], bhs[32], bws[32], gngs[32], gnbs[32];
    __shared__ float mus[32], rstds[32];

    const int bid = blockIdx.x;
    const int t   = threadIdx.x;         // 0..1023

    if (bid >= NKS) {
        // =================== channel role: 16 x0 planes ===================
        const int k    = bid - NKS;      // 0..511
        const int bg   = k >> 1;         // 0..255
        const int half = (k & 1) * 16;   // plane half base: 0 or 16
        const int gq   = t >> 8;         // sub-group 0..3
        const int tt   = t & 255;        // thread within sub-group
        const int n    = bg >> 3;
        const int g    = bg & 7;

        float* cws   = &s_row[0][0];     // [4][8] warp partials
        float* gates = &s_col[0][0];     // [4] gates

        #pragma unroll
        for (int pl = 0; pl < 4; pl++) {
            const int cc = half + gq * 4 + pl;   // plane 0..31

            const float4* p4 = (const float4*)(x + (size_t)(n * CTOT + g * 64 + cc) * PLANE);
            float4 v[4];
            #pragma unroll
            for (int i = 0; i < 4; i++) v[i] = __ldcs(&p4[tt + 256 * i]);

            float s = 0.f;
            #pragma unroll
            for (int i = 0; i < 4; i++) s += v[i].x + v[i].y + v[i].z + v[i].w;
            #pragma unroll
            for (int o = 16; o > 0; o >>= 1) s += __shfl_xor_sync(0xffffffffu, s, o);
            if ((tt & 31) == 0) cws[gq * 8 + (tt >> 5)] = s;
            __syncthreads();
            if (tt == 0) {
                float tot = 0.f;
                #pragma unroll
                for (int i = 0; i < 8; i++) tot += cws[gq * 8 + i];
                float gap = tot * (1.0f / 4096.0f);
                gates[gq] = sigmoid_exact(cweight[cc] * gap + cbias[cc]);
            }
            __syncthreads();
            const float gate = gates[gq];

            const int c_prev  = g * 64 + cc;
            const int c_final = 2 * (c_prev & 255) + (c_prev >> 8);
            float4* o4 = (float4*)(out + (size_t)(n * CTOT + c_final) * PLANE);
            #pragma unroll
            for (int i = 0; i < 4; i++) {
                float4 r = v[i];
                r.x *= gate; r.y *= gate; r.z *= gate; r.w *= gate;
                __stcs(&o4[tt + 256 * i], r);
            }
        }
        return;
    }

    // =================== ks role: spatial branch for one bg ===================
    const int bg   = bid;            // 0..255
    const int n    = bg >> 3;
    const int g    = bg & 7;
    const int wid  = t >> 5;         // plane index 0..31
    const int lane = t & 31;

    // weights (independent; issued first)
    w1s[t] = w1[t];
    whs[t] = wh[t];
    wws[t] = wwv[t];
    if (t < 32) {
        b1s[t] = b1[t]; bhs[t] = bh[t]; bws[t] = bw[t];
        gngs[t] = gng[t]; gnbs[t] = gnb[t];
    }

    // ---------------- phase 1: reductions (warp w = plane w) ----------------
    const float4* p4 = (const float4*)(x + (size_t)(n * CTOT + g * 64 + 32 + wid) * PLANE);
    // lane reads float4 j = lane + 32*i : row = (lane>>4) + 2*i, cols 4*(lane&15)..+3
    float4 colacc = make_float4(0.f, 0.f, 0.f, 0.f);
    #pragma unroll 8
    for (int i = 0; i < 32; i++) {
        float4 v = p4[lane + 32 * i];            // default policy: retain in L2
        colacc.x += v.x; colacc.y += v.y; colacc.z += v.z; colacc.w += v.w;
        float s = v.x + v.y + v.z + v.w;
        s += __shfl_xor_sync(0xffffffffu, s, 8);
        s += __shfl_xor_sync(0xffffffffu, s, 4);
        s += __shfl_xor_sync(0xffffffffu, s, 2);
        s += __shfl_xor_sync(0xffffffffu, s, 1);
        if ((lane & 15) == 0)
            s_row[wid][2 * i + (lane >> 4)] = s * (1.0f / 64.0f);
    }
    // fold the two half-warps' row sets for columns
    colacc.x += __shfl_xor_sync(0xffffffffu, colacc.x, 16);
    colacc.y += __shfl_xor_sync(0xffffffffu, colacc.y, 16);
    colacc.z += __shfl_xor_sync(0xffffffffu, colacc.z, 16);
    colacc.w += __shfl_xor_sync(0xffffffffu, colacc.w, 16);
    if (lane < 16) {
        float4 cw;
        cw.x = colacc.x * (1.0f / 64.0f);
        cw.y = colacc.y * (1.0f / 64.0f);
        cw.z = colacc.z * (1.0f / 64.0f);
        cw.w = colacc.w * (1.0f / 64.0f);
        ((float4*)s_col[wid])[lane] = cw;
    }
    float cs = colacc.x + colacc.y + colacc.z + colacc.w;
    cs += __shfl_xor_sync(0xffffffffu, cs, 8);
    cs += __shfl_xor_sync(0xffffffffu, cs, 4);
    cs += __shfl_xor_sync(0xffffffffu, cs, 2);
    cs += __shfl_xor_sync(0xffffffffu, cs, 1);
    if (lane == 0) s_xs[wid] = cs * (1.0f / 4096.0f);
    __syncthreads();

    // ---------------- phase 2: conv1 -> GN -> h-swish -> convh/convw --------
    const int p  = t & 127;          // position 0..127
    const int oh = (t >> 7) * 16;    // only meaningful for t<256

    float a1[16];
    if (t < 256) {
        #pragma unroll
        for (int o = 0; o < 16; o++) a1[o] = b1s[oh + o];
        #pragma unroll
        for (int i = 0; i < 32; i++) {
            const float ci = (p < 64) ? s_row[i][p] : s_col[i][p - 64];
            #pragma unroll
            for (int o = 0; o < 16; o++)
                a1[o] += w1s[(oh + o) * 32 + i] * ci;
        }
    }
    __syncthreads();                 // s_row/s_col reads done -> reusable
    if (t < 256) {
        #pragma unroll
        for (int o = 0; o < 16; o++) ybuf[oh + o][p] = a1[o];
    }
    __syncthreads();

    if (t < 256) {                   // GN stats: warp w2 handles 4 channels
        const int w2 = t >> 5, l = t & 31;
        #pragma unroll
        for (int j = 0; j < 4; j++) {
            const int o = w2 * 4 + j;
            float e0 = ybuf[o][l],      e1 = ybuf[o][l + 32],
                  e2 = ybuf[o][l + 64], e3 = ybuf[o][l + 96];
            float s  = e0 + e1 + e2 + e3;
            float ss = e0 * e0 + e1 * e1 + e2 * e2 + e3 * e3;
            #pragma unroll
            for (int off = 16; off > 0; off >>= 1) {
                s  += __shfl_xor_sync(0xffffffffu, s, off);
                ss += __shfl_xor_sync(0xffffffffu, ss, off);
            }
            if (l == 0) {
                float mu  = s * (1.0f / 128.0f);
                float var = ss * (1.0f / 128.0f) - mu * mu;
                mus[o]   = mu;
                rstds[o] = rsqrtf(var + 1e-5f);
            }
        }
    }
    __syncthreads();

    if (t < 256) {                   // normalize + affine + h-swish
        #pragma unroll
        for (int j = 0; j < 16; j++) {
            const int k = oh + j;
            float v = (ybuf[k][p] - mus[k]) * rstds[k] * gngs[k] + gnbs[k];
            float hs = fminf(fmaxf(v + 3.0f, 0.0f), 6.0f) * (1.0f / 6.0f);
            ybuf[k][p] = v * hs;
        }
    }
    __syncthreads();

    if (t < 256) {                   // convh (p<64) -> s_row, convw -> s_col
        const int half = p >> 6;
        const int r    = p & 63;
        const float* wsel = half ? wws : whs;
        const float* bsel = half ? bws : bhs;
        float a2[16];
        #pragma unroll
        for (int o = 0; o < 16; o++) a2[o] = bsel[oh + o];
        #pragma unroll
        for (int i = 0; i < 32; i++) {
            const float ci = ybuf[i][p];
            #pragma unroll
            for (int o = 0; o < 16; o++)
                a2[o] += wsel[(oh + o) * 32 + i] * ci;
        }
        if (half) {
            #pragma unroll
            for (int o = 0; o < 16; o++) s_col[oh + o][r] = a2[o];   // a_w
        } else {
            #pragma unroll
            for (int o = 0; o < 16; o++) s_row[oh + o][r] = a2[o];   // a_h
        }
    }
    __syncthreads();

    // ---------------- phase 3: gate + write (warp w = plane w) --------------
    const float xs = s_xs[wid];
    float4 aw4 = ((float4*)s_col[wid])[lane & 15];
    aw4.x *= xs; aw4.y *= xs; aw4.z *= xs; aw4.w *= xs;

    const int c_prev  = g * 64 + 32 + wid;
    const int c_final = 2 * (c_prev & 255) + (c_prev >> 8);
    float4* o4 = (float4*)(out + (size_t)(n * CTOT + c_final) * PLANE);

    #pragma unroll 8
    for (int i = 0; i < 32; i++) {
        float4 v = __ldcs(&p4[lane + 32 * i]);            // hot in L2
        const float ah = s_row[wid][2 * i + (lane >> 4)];
        v.x *= sigmoid_fast(ah * aw4.x);
        v.y *= sigmoid_fast(ah * aw4.y);
        v.z *= sigmoid_fast(ah * aw4.z);
        v.w *= sigmoid_fast(ah * aw4.w);
        __stcs(&o4[lane + 32 * i], v);
    }
}

// ---------------------------------------------------------------------------
extern "C" void kernel_launch(void* const* d_in, const int* in_sizes, int n_in,
                              void* d_out, int out_size)
{
    const float* x       = (const float*)d_in[0];
    const float* cweight = (const float*)d_in[1];
    const float* cbias   = (const float*)d_in[2];
    const float* conv1_w = (const float*)d_in[3];
    const float* conv1_b = (const float*)d_in[4];
    const float* gn_g    = (const float*)d_in[5];
    const float* gn_b    = (const float*)d_in[6];
    const float* convh_w = (const float*)d_in[7];
    const float* convh_b = (const float*)d_in[8];
    const float* convw_w = (const float*)d_in[9];
    const float* convw_b = (const float*)d_in[10];
    float* out = (float*)d_out;

    fused_kernel<<<NKS + NCH, 1024>>>(
        x, cweight, cbias,
        conv1_w, conv1_b, gn_g, gn_b,
        convh_w, convh_b, convw_w, convw_b,
        out);
}